// round 8
// baseline (speedup 1.0000x reference)
#include <cuda_runtime.h>
#include <math.h>

#define B_ 8
#define N_ 65536
#define M_ 8
#define NBLK 128
#define RED_THREADS 256
#define C_THREADS 256
#define TILE_CELLS 256
#define GRID2 (((N_ / TILE_CELLS)) * B_)   // 2048 apply blocks

// Scratch (no cudaMalloc allowed)
__device__ float g_partials[B_ * NBLK * 16];          // [b][blk][16]
__device__ __align__(16) float g_comb[B_ * 16];       // [b][16]
__device__ unsigned g_flag = 0;
__device__ unsigned g_done = 0;

// ---------------------------------------------------------------------------
// Compile-time Cayley sign for Cl(3,0,1), replicating the reference loop.
// ---------------------------------------------------------------------------
__host__ __device__ constexpr int cpop4(unsigned v) {
    return (int)((v & 1u) + ((v >> 1) & 1u) + ((v >> 2) & 1u) + ((v >> 3) & 1u));
}
__host__ __device__ constexpr float csign(int i, int j) {
    float s = 1.0f;
    for (int b = 0; b < 4; b++) {
        if ((j >> b) & 1) {
            if (cpop4((unsigned)(i >> (b + 1))) & 1) s = -s;
            if ((i >> b) & 1) {
                if (b == 0) s = 0.0f;  // metric[0] = 0
            }
        }
    }
    return s;
}

// smem transpose swizzle: quarter q of local cell c -> f4 slot
__device__ __forceinline__ int swz(int c, int q) {
    return (c << 2) + (q ^ ((c ^ (c >> 2)) & 3));
}

// ---------------------------------------------------------------------------
// Kernel A: partial sums of cpu_state over N, per batch. (round-5, unchanged)
// ---------------------------------------------------------------------------
__global__ void gss_reduce_kernel(const float* __restrict__ cpu_state) {
    int b = blockIdx.y;
    const float4* src = (const float4*)(cpu_state + (size_t)b * N_ * 16);
    const int T = NBLK * RED_THREADS;            // 32768 threads per batch
    int t = blockIdx.x * RED_THREADS + threadIdx.x;

    float4 v0 = src[t + 0 * T];
    float4 v1 = src[t + 1 * T];
    float4 v2 = src[t + 2 * T];
    float4 v3 = src[t + 3 * T];
    float4 v4 = src[t + 4 * T];
    float4 v5 = src[t + 5 * T];
    float4 v6 = src[t + 6 * T];
    float4 v7 = src[t + 7 * T];

    float4 acc;
    acc.x = ((v0.x + v1.x) + (v2.x + v3.x)) + ((v4.x + v5.x) + (v6.x + v7.x));
    acc.y = ((v0.y + v1.y) + (v2.y + v3.y)) + ((v4.y + v5.y) + (v6.y + v7.y));
    acc.z = ((v0.z + v1.z) + (v2.z + v3.z)) + ((v4.z + v5.z) + (v6.z + v7.z));
    acc.w = ((v0.w + v1.w) + (v2.w + v3.w)) + ((v4.w + v5.w) + (v6.w + v7.w));

    int lane = threadIdx.x & 31;
    int warp = threadIdx.x >> 5;
#pragma unroll
    for (int off = 16; off >= 4; off >>= 1) {
        acc.x += __shfl_xor_sync(0xffffffffu, acc.x, off);
        acc.y += __shfl_xor_sync(0xffffffffu, acc.y, off);
        acc.z += __shfl_xor_sync(0xffffffffu, acc.z, off);
        acc.w += __shfl_xor_sync(0xffffffffu, acc.w, off);
    }
    __shared__ float4 sm[8][4];
    if (lane < 4) sm[warp][lane] = acc;   // lane==q holds quarter q
    __syncthreads();
    if (warp == 0) {
        float4 a2 = sm[lane >> 2][lane & 3];
#pragma unroll
        for (int off = 16; off >= 4; off >>= 1) {
            a2.x += __shfl_xor_sync(0xffffffffu, a2.x, off);
            a2.y += __shfl_xor_sync(0xffffffffu, a2.y, off);
            a2.z += __shfl_xor_sync(0xffffffffu, a2.z, off);
            a2.w += __shfl_xor_sync(0xffffffffu, a2.w, off);
        }
        if (lane < 4) {
            float* dst = g_partials + (b * NBLK + blockIdx.x) * 16 + lane * 4;
            dst[0] = a2.x; dst[1] = a2.y; dst[2] = a2.z; dst[3] = a2.w;
        }
    }
}

// ---------------------------------------------------------------------------
// Threefry-2x32 (JAX partitionable scheme: counter (0, e), bits = o0^o1)
// ---------------------------------------------------------------------------
__device__ __forceinline__ unsigned tf_rotl(unsigned v, int d) {
    return (v << d) | (v >> (32 - d));
}

__device__ void threefry2x32(unsigned k0, unsigned k1,
                             unsigned c0, unsigned c1,
                             unsigned& o0, unsigned& o1) {
    unsigned ks0 = k0, ks1 = k1, ks2 = k0 ^ k1 ^ 0x1BD11BDAu;
    unsigned x0 = c0 + ks0;
    unsigned x1 = c1 + ks1;
    const int r0[4] = {13, 15, 26, 6};
    const int r1[4] = {17, 29, 16, 24};
#define TF_BLOCK(R)                                            \
    {                                                          \
        _Pragma("unroll")                                      \
        for (int q = 0; q < 4; q++) {                          \
            x0 += x1;                                          \
            x1 = tf_rotl(x1, (R)[q]);                          \
            x1 ^= x0;                                          \
        }                                                      \
    }
    TF_BLOCK(r0); x0 += ks1; x1 += ks2 + 1u;
    TF_BLOCK(r1); x0 += ks2; x1 += ks0 + 2u;
    TF_BLOCK(r0); x0 += ks0; x1 += ks1 + 3u;
    TF_BLOCK(r1); x0 += ks1; x1 += ks2 + 4u;
    TF_BLOCK(r0); x0 += ks2; x1 += ks0 + 5u;
#undef TF_BLOCK
    o0 = x0; o1 = x1;
}

// ---------------------------------------------------------------------------
// Kernel C: apply + embedded scoring (block (0,0) only) behind a one-way flag.
// All blocks: load tile -> [block(0,0): scoring -> g_comb -> flag] ->
// wait flag -> geometric product -> store tile.
// ---------------------------------------------------------------------------
__global__ void __launch_bounds__(C_THREADS)
gss_apply_kernel(const float* __restrict__ state,
                 const float* __restrict__ ctrl,
                 const float* __restrict__ rule_mem,
                 const float* __restrict__ templates,
                 const float* __restrict__ W1,
                 const float* __restrict__ b1,
                 const float* __restrict__ W2,
                 const float* __restrict__ b2,
                 const float* __restrict__ Wr,
                 const float* __restrict__ br,
                 const float* __restrict__ log_temp,
                 float* __restrict__ out) {
    int b = blockIdx.y;
    int tid = threadIdx.x;
    int lane = tid & 31;
    int warp = tid >> 5;

    __shared__ float4 sm[TILE_CELLS * 4];  // 16 KB tile

    // scoring scratch (static smem, ~8 KB)
    __shared__ float summ[B_][16];
    __shared__ float si[B_][9];
    __shared__ float hid[B_][64];
    __shared__ float sc[B_][8];
    __shared__ float rs[B_][16];
    __shared__ float rmod[B_][128];
    __shared__ float wts[B_][8];

    const size_t base4 = (size_t)b * N_ * 4 + (size_t)blockIdx.x * TILE_CELLS * 4;
    const float4* src = (const float4*)state + base4;
    float4* dst = (float4*)out + base4;

    // Phase 1: coalesced global load -> swizzled smem (useful prefetch for all)
#pragma unroll
    for (int k = 0; k < 4; k++) {
        int L = k * C_THREADS + tid;
        float4 v = __ldcg(src + L);
        sm[swz(L >> 2, L & 3)] = v;
    }
    __syncthreads();

    if (blockIdx.x == 0 && b == 0) {
        // ---- scoring pipeline: 8 warps, one batch each (round-5 validated)
        int bb = warp;

        if (lane < 16) {
            float s = 0.f;
#pragma unroll 8
            for (int blk = 0; blk < NBLK; blk++)
                s += g_partials[(bb * NBLK + blk) * 16 + lane];
            summ[bb][lane] = s * (1.0f / N_);
        }
        __syncwarp();

        if (lane < 5) {
            float s = 0.f;
            for (int d = 0; d < 16; d++)
                if (__popc(d) == lane) { float v = summ[bb][d]; s += v * v; }
            si[bb][lane] = sqrtf(s + 1e-12f);
        }
        if (lane >= 5 && lane < 9) si[bb][lane] = ctrl[bb * 4 + (lane - 5)];
        __syncwarp();

        for (int h = lane; h < 64; h += 32) {
            float a = b1[h];
#pragma unroll
            for (int i = 0; i < 9; i++) a += si[bb][i] * W1[i * 64 + h];
            hid[bb][h] = fmaxf(a, 0.f);
        }
        __syncwarp();

        if (lane < 8) {
            float a = b2[lane];
            for (int h = 0; h < 64; h++) a += hid[bb][h] * W2[h * 8 + lane];
            sc[bb][lane] = a;
        }

        if (lane < 16) {
            float s = 0.f;
            for (int m = 0; m < M_; m++) s += rule_mem[(bb * M_ + m) * 16 + lane];
            rs[bb][lane] = s * (1.0f / M_);
        }
        __syncwarp();

        for (int j = lane; j < 128; j += 32) {
            float a = br[j];
#pragma unroll
            for (int d = 0; d < 16; d++) a += rs[bb][d] * Wr[d * 128 + j];
            rmod[bb][j] = a;
        }
        __syncwarp();

        if (lane < 8) {
            int e = bb * 8 + lane;
            unsigned o0, o1;
            threefry2x32(0u, 42u, 0u, (unsigned)e, o0, o1);
            unsigned bits = o0 ^ o1;
            float u = __uint_as_float((bits >> 9) | 0x3f800000u) - 1.0f;
            const float minv = 1e-6f, maxv = 1.0f - 1e-6f;
            u = fmaxf(minv, u * (maxv - minv) + minv);
            float g = -logf(-logf(u));
            float tau = fminf(fmaxf(expf(log_temp[0]), 0.1f), 5.0f);
            wts[bb][lane] = (sc[bb][lane] + g) / tau;
        }
        __syncwarp();

        if (lane == 0) {
            float mx = -1e30f;
            for (int k = 0; k < 8; k++) mx = fmaxf(mx, wts[bb][k]);
            float s = 0.f;
            for (int k = 0; k < 8; k++) { float e = expf(wts[bb][k] - mx); wts[bb][k] = e; s += e; }
            float inv = 1.0f / s;
            for (int k = 0; k < 8; k++) wts[bb][k] *= inv;
        }
        __syncwarp();

        if (lane < 16) {
            float s = 0.f;
            for (int k = 0; k < 8; k++) {
                float t = templates[k * 16 + lane] + rmod[bb][k * 16 + lane];
                s += wts[bb][k] * sc[bb][k] * t;
            }
            g_comb[bb * 16 + lane] = s;
        }
        __syncthreads();                    // all 8 scoring warps done
        if (tid == 0) {
            __threadfence();                // release g_comb
            atomicExch(&g_flag, 1u);
        }
    } else {
        // wait for scoring flag (one-way; block (0,0) is in wave 1 -> no deadlock)
        if (tid == 0) {
            while (atomicAdd(&g_flag, 0u) == 0u) __nanosleep(64);
            __threadfence();                // acquire
        }
        __syncthreads();
    }

    // comb for this batch (L2-fresh via __ldcg)
    const float4* cp = (const float4*)(g_comb + b * 16);
    float4 a0 = __ldcg(cp + 0), a1 = __ldcg(cp + 1),
           a2 = __ldcg(cp + 2), a3 = __ldcg(cp + 3);
    float a[16] = {a0.x, a0.y, a0.z, a0.w, a1.x, a1.y, a1.z, a1.w,
                   a2.x, a2.y, a2.z, a2.w, a3.x, a3.y, a3.z, a3.w};

    // Phase 2: this thread's cell from smem (conflict-free via swizzle)
    float x[16];
#pragma unroll
    for (int q = 0; q < 4; q++) {
        float4 v = sm[swz(tid, q)];
        x[q * 4 + 0] = v.x; x[q * 4 + 1] = v.y; x[q * 4 + 2] = v.z; x[q * 4 + 3] = v.w;
    }

    float y[16];
#pragma unroll
    for (int l = 0; l < 16; l++) {
        float s = 0.f;
#pragma unroll
        for (int j = 0; j < 16; j++) {
            const float sgn = csign(j ^ l, j);   // compile-time constant
            if (sgn > 0.5f)       s = fmaf(a[j ^ l],  x[j], s);
            else if (sgn < -0.5f) s = fmaf(-a[j ^ l], x[j], s);
        }
        y[l] = s;
    }
    __syncthreads();  // tile buffer reuse

    // Phase 3: y -> swizzled smem
#pragma unroll
    for (int q = 0; q < 4; q++)
        sm[swz(tid, q)] = make_float4(y[q * 4 + 0], y[q * 4 + 1], y[q * 4 + 2], y[q * 4 + 3]);
    __syncthreads();

    // Phase 4: coalesced store out (evict-first: protect cpu_state in L2)
#pragma unroll
    for (int k = 0; k < 4; k++) {
        int L = k * C_THREADS + tid;
        __stcs(dst + L, sm[swz(L >> 2, L & 3)]);
    }

    // reset flag for next graph replay: last block to finish clears it
    if (tid == 0) {
        if (atomicAdd(&g_done, 1u) == (unsigned)(GRID2 - 1)) {
            g_flag = 0;
            g_done = 0;
        }
    }
}

extern "C" void kernel_launch(void* const* d_in, const int* in_sizes, int n_in,
                              void* d_out, int out_size) {
    const float* cpu_state   = (const float*)d_in[0];
    const float* ctrl_cursor = (const float*)d_in[1];
    const float* rule_memory = (const float*)d_in[2];
    const float* templates   = (const float*)d_in[3];
    const float* W1          = (const float*)d_in[4];
    const float* b1          = (const float*)d_in[5];
    const float* W2          = (const float*)d_in[6];
    const float* b2          = (const float*)d_in[7];
    const float* Wr          = (const float*)d_in[8];
    const float* br          = (const float*)d_in[9];
    const float* log_temp    = (const float*)d_in[10];
    float* out = (float*)d_out;

    dim3 gA(NBLK, B_);
    gss_reduce_kernel<<<gA, RED_THREADS>>>(cpu_state);

    dim3 gC(N_ / TILE_CELLS, B_);
    gss_apply_kernel<<<gC, C_THREADS>>>(cpu_state, ctrl_cursor, rule_memory,
                                        templates, W1, b1, W2, b2, Wr, br,
                                        log_temp, out);
}

// round 9
// speedup vs baseline: 1.5824x; 1.5824x over previous
#include <cuda_runtime.h>
#include <math.h>

#define B_ 8
#define N_ 65536
#define M_ 8
#define NBLK 128
#define RED_THREADS 256
#define C_THREADS 256
#define TILE_CELLS 256

// Scratch (no cudaMalloc allowed)
__device__ float g_partials[B_ * NBLK * 16];          // [b][blk][16]
__device__ __align__(16) float g_comb[B_ * 16];       // [b][16]

// ---------------------------------------------------------------------------
// Compile-time Cayley sign for Cl(3,0,1), replicating the reference loop.
// ---------------------------------------------------------------------------
__host__ __device__ constexpr int cpop4(unsigned v) {
    return (int)((v & 1u) + ((v >> 1) & 1u) + ((v >> 2) & 1u) + ((v >> 3) & 1u));
}
__host__ __device__ constexpr float csign(int i, int j) {
    float s = 1.0f;
    for (int b = 0; b < 4; b++) {
        if ((j >> b) & 1) {
            if (cpop4((unsigned)(i >> (b + 1))) & 1) s = -s;
            if ((i >> b) & 1) {
                if (b == 0) s = 0.0f;  // metric[0] = 0
            }
        }
    }
    return s;
}

// smem transpose swizzle: quarter q of local cell c -> f4 slot
__device__ __forceinline__ int swz(int c, int q) {
    return (c << 2) + (q ^ ((c ^ (c >> 2)) & 3));
}

// ---------------------------------------------------------------------------
// Kernel A: partial sums of cpu_state over N, per batch.
// __ldcg: land in L2 (for apply's reuse) without polluting L1.
// ---------------------------------------------------------------------------
__global__ void gss_reduce_kernel(const float* __restrict__ cpu_state) {
    int b = blockIdx.y;
    const float4* src = (const float4*)(cpu_state + (size_t)b * N_ * 16);
    const int T = NBLK * RED_THREADS;            // 32768 threads per batch
    int t = blockIdx.x * RED_THREADS + threadIdx.x;

    float4 v0 = __ldcg(src + t + 0 * T);
    float4 v1 = __ldcg(src + t + 1 * T);
    float4 v2 = __ldcg(src + t + 2 * T);
    float4 v3 = __ldcg(src + t + 3 * T);
    float4 v4 = __ldcg(src + t + 4 * T);
    float4 v5 = __ldcg(src + t + 5 * T);
    float4 v6 = __ldcg(src + t + 6 * T);
    float4 v7 = __ldcg(src + t + 7 * T);

    float4 acc;
    acc.x = ((v0.x + v1.x) + (v2.x + v3.x)) + ((v4.x + v5.x) + (v6.x + v7.x));
    acc.y = ((v0.y + v1.y) + (v2.y + v3.y)) + ((v4.y + v5.y) + (v6.y + v7.y));
    acc.z = ((v0.z + v1.z) + (v2.z + v3.z)) + ((v4.z + v5.z) + (v6.z + v7.z));
    acc.w = ((v0.w + v1.w) + (v2.w + v3.w)) + ((v4.w + v5.w) + (v6.w + v7.w));

    int lane = threadIdx.x & 31;
    int warp = threadIdx.x >> 5;
#pragma unroll
    for (int off = 16; off >= 4; off >>= 1) {
        acc.x += __shfl_xor_sync(0xffffffffu, acc.x, off);
        acc.y += __shfl_xor_sync(0xffffffffu, acc.y, off);
        acc.z += __shfl_xor_sync(0xffffffffu, acc.z, off);
        acc.w += __shfl_xor_sync(0xffffffffu, acc.w, off);
    }
    __shared__ float4 sm[8][4];
    if (lane < 4) sm[warp][lane] = acc;   // lane==q holds quarter q
    __syncthreads();
    if (warp == 0) {
        float4 a2 = sm[lane >> 2][lane & 3];
#pragma unroll
        for (int off = 16; off >= 4; off >>= 1) {
            a2.x += __shfl_xor_sync(0xffffffffu, a2.x, off);
            a2.y += __shfl_xor_sync(0xffffffffu, a2.y, off);
            a2.z += __shfl_xor_sync(0xffffffffu, a2.z, off);
            a2.w += __shfl_xor_sync(0xffffffffu, a2.w, off);
        }
        if (lane < 4) {
            float* dst = g_partials + (b * NBLK + blockIdx.x) * 16 + lane * 4;
            dst[0] = a2.x; dst[1] = a2.y; dst[2] = a2.z; dst[3] = a2.w;
        }
    }
}

// ---------------------------------------------------------------------------
// Threefry-2x32 (JAX partitionable scheme: counter (0, e), bits = o0^o1)
// ---------------------------------------------------------------------------
__device__ __forceinline__ unsigned tf_rotl(unsigned v, int d) {
    return (v << d) | (v >> (32 - d));
}

__device__ void threefry2x32(unsigned k0, unsigned k1,
                             unsigned c0, unsigned c1,
                             unsigned& o0, unsigned& o1) {
    unsigned ks0 = k0, ks1 = k1, ks2 = k0 ^ k1 ^ 0x1BD11BDAu;
    unsigned x0 = c0 + ks0;
    unsigned x1 = c1 + ks1;
    const int r0[4] = {13, 15, 26, 6};
    const int r1[4] = {17, 29, 16, 24};
#define TF_BLOCK(R)                                            \
    {                                                          \
        _Pragma("unroll")                                      \
        for (int q = 0; q < 4; q++) {                          \
            x0 += x1;                                          \
            x1 = tf_rotl(x1, (R)[q]);                          \
            x1 ^= x0;                                          \
        }                                                      \
    }
    TF_BLOCK(r0); x0 += ks1; x1 += ks2 + 1u;
    TF_BLOCK(r1); x0 += ks2; x1 += ks0 + 2u;
    TF_BLOCK(r0); x0 += ks0; x1 += ks1 + 3u;
    TF_BLOCK(r1); x0 += ks1; x1 += ks2 + 4u;
    TF_BLOCK(r0); x0 += ks2; x1 += ks0 + 5u;
#undef TF_BLOCK
    o0 = x0; o1 = x1;
}

// ---------------------------------------------------------------------------
// Kernel B: tiny per-batch pipeline. One warp per batch. Publishes g_comb.
// ---------------------------------------------------------------------------
__global__ void gss_small_kernel(const float* __restrict__ ctrl,
                                 const float* __restrict__ rule_mem,
                                 const float* __restrict__ templates,
                                 const float* __restrict__ W1,
                                 const float* __restrict__ b1,
                                 const float* __restrict__ W2,
                                 const float* __restrict__ b2,
                                 const float* __restrict__ Wr,
                                 const float* __restrict__ br,
                                 const float* __restrict__ log_temp) {
    __shared__ float summ[B_][16];
    __shared__ float si[B_][9];
    __shared__ float hid[B_][64];
    __shared__ float sc[B_][8];
    __shared__ float rs[B_][16];
    __shared__ float rmod[B_][128];
    __shared__ float wts[B_][8];

    int warp = threadIdx.x >> 5;
    int lane = threadIdx.x & 31;
    int b = warp;  // 8 warps, one per batch

    if (lane < 16) {
        float s = 0.f;
#pragma unroll 8
        for (int blk = 0; blk < NBLK; blk++)
            s += g_partials[(b * NBLK + blk) * 16 + lane];
        summ[b][lane] = s * (1.0f / N_);
    }
    __syncwarp();

    if (lane < 5) {
        float s = 0.f;
        for (int d = 0; d < 16; d++)
            if (__popc(d) == lane) { float v = summ[b][d]; s += v * v; }
        si[b][lane] = sqrtf(s + 1e-12f);
    }
    if (lane >= 5 && lane < 9) si[b][lane] = ctrl[b * 4 + (lane - 5)];
    __syncwarp();

    for (int h = lane; h < 64; h += 32) {
        float a = b1[h];
#pragma unroll
        for (int i = 0; i < 9; i++) a += si[b][i] * W1[i * 64 + h];
        hid[b][h] = fmaxf(a, 0.f);
    }
    __syncwarp();

    if (lane < 8) {
        float a = b2[lane];
        for (int h = 0; h < 64; h++) a += hid[b][h] * W2[h * 8 + lane];
        sc[b][lane] = a;
    }

    if (lane < 16) {
        float s = 0.f;
        for (int m = 0; m < M_; m++) s += rule_mem[(b * M_ + m) * 16 + lane];
        rs[b][lane] = s * (1.0f / M_);
    }
    __syncwarp();

    for (int j = lane; j < 128; j += 32) {
        float a = br[j];
#pragma unroll
        for (int d = 0; d < 16; d++) a += rs[b][d] * Wr[d * 128 + j];
        rmod[b][j] = a;
    }
    __syncwarp();

    if (lane < 8) {
        int e = b * 8 + lane;
        unsigned o0, o1;
        threefry2x32(0u, 42u, 0u, (unsigned)e, o0, o1);
        unsigned bits = o0 ^ o1;
        float u = __uint_as_float((bits >> 9) | 0x3f800000u) - 1.0f;
        const float minv = 1e-6f, maxv = 1.0f - 1e-6f;
        u = fmaxf(minv, u * (maxv - minv) + minv);
        float g = -logf(-logf(u));
        float tau = fminf(fmaxf(expf(log_temp[0]), 0.1f), 5.0f);
        wts[b][lane] = (sc[b][lane] + g) / tau;
    }
    __syncwarp();

    if (lane == 0) {
        float mx = -1e30f;
        for (int k = 0; k < 8; k++) mx = fmaxf(mx, wts[b][k]);
        float s = 0.f;
        for (int k = 0; k < 8; k++) { float e = expf(wts[b][k] - mx); wts[b][k] = e; s += e; }
        float inv = 1.0f / s;
        for (int k = 0; k < 8; k++) wts[b][k] *= inv;
    }
    __syncwarp();

    if (lane < 16) {
        float s = 0.f;
        for (int k = 0; k < 8; k++) {
            float t = templates[k * 16 + lane] + rmod[b][k * 16 + lane];
            s += wts[b][k] * sc[b][k] * t;
        }
        g_comb[b * 16 + lane] = s;
    }
}

// ---------------------------------------------------------------------------
// Kernel C: geometric product via shared-memory transpose tile.
// Phase 1 uses cp.async.cg (LDGSTS): gmem(L2) -> smem directly, no register
// round-trip, no L1 pass. Remaining phases as round 5 (27.1us validated).
// ---------------------------------------------------------------------------
__global__ void __launch_bounds__(C_THREADS)
gss_apply_kernel(const float* __restrict__ state, float* __restrict__ out) {
    int b = blockIdx.y;
    int tid = threadIdx.x;

    __shared__ float4 sm[TILE_CELLS * 4];  // 16 KB

    const size_t base4 = (size_t)b * N_ * 4 + (size_t)blockIdx.x * TILE_CELLS * 4;
    const float4* src = (const float4*)state + base4;
    float4* dst = (float4*)out + base4;

    // comb in registers (uniform per batch; L2 broadcast) - issue early
    const float4* cp = (const float4*)(g_comb + b * 16);
    float4 a0 = __ldg(cp + 0), a1 = __ldg(cp + 1), a2 = __ldg(cp + 2), a3 = __ldg(cp + 3);

    // Phase 1: cp.async 16B copies, coalesced gmem -> swizzled smem
#pragma unroll
    for (int k = 0; k < 4; k++) {
        int L = k * C_THREADS + tid;
        unsigned sa = (unsigned)__cvta_generic_to_shared(&sm[swz(L >> 2, L & 3)]);
        asm volatile("cp.async.cg.shared.global [%0], [%1], 16;\n"
                     :: "r"(sa), "l"(src + L) : "memory");
    }
    asm volatile("cp.async.commit_group;\n" ::: "memory");
    asm volatile("cp.async.wait_group 0;\n" ::: "memory");
    __syncthreads();

    float a[16] = {a0.x, a0.y, a0.z, a0.w, a1.x, a1.y, a1.z, a1.w,
                   a2.x, a2.y, a2.z, a2.w, a3.x, a3.y, a3.z, a3.w};

    // Phase 2: this thread's cell from smem (conflict-free via swizzle)
    float x[16];
#pragma unroll
    for (int q = 0; q < 4; q++) {
        float4 v = sm[swz(tid, q)];
        x[q * 4 + 0] = v.x; x[q * 4 + 1] = v.y; x[q * 4 + 2] = v.z; x[q * 4 + 3] = v.w;
    }

    float y[16];
#pragma unroll
    for (int l = 0; l < 16; l++) {
        float s = 0.f;
#pragma unroll
        for (int j = 0; j < 16; j++) {
            const float sgn = csign(j ^ l, j);   // compile-time constant
            if (sgn > 0.5f)       s = fmaf(a[j ^ l],  x[j], s);
            else if (sgn < -0.5f) s = fmaf(-a[j ^ l], x[j], s);
        }
        y[l] = s;
    }
    __syncthreads();  // tile buffer reuse

    // Phase 3: y -> swizzled smem
#pragma unroll
    for (int q = 0; q < 4; q++)
        sm[swz(tid, q)] = make_float4(y[q * 4 + 0], y[q * 4 + 1], y[q * 4 + 2], y[q * 4 + 3]);
    __syncthreads();

    // Phase 4: coalesced store out (evict-first: protect cpu_state in L2)
#pragma unroll
    for (int k = 0; k < 4; k++) {
        int L = k * C_THREADS + tid;
        __stcs(dst + L, sm[swz(L >> 2, L & 3)]);
    }
}

extern "C" void kernel_launch(void* const* d_in, const int* in_sizes, int n_in,
                              void* d_out, int out_size) {
    const float* cpu_state   = (const float*)d_in[0];
    const float* ctrl_cursor = (const float*)d_in[1];
    const float* rule_memory = (const float*)d_in[2];
    const float* templates   = (const float*)d_in[3];
    const float* W1          = (const float*)d_in[4];
    const float* b1          = (const float*)d_in[5];
    const float* W2          = (const float*)d_in[6];
    const float* b2          = (const float*)d_in[7];
    const float* Wr          = (const float*)d_in[8];
    const float* br          = (const float*)d_in[9];
    const float* log_temp    = (const float*)d_in[10];
    float* out = (float*)d_out;

    dim3 gA(NBLK, B_);
    gss_reduce_kernel<<<gA, RED_THREADS>>>(cpu_state);

    gss_small_kernel<<<1, 256>>>(ctrl_cursor, rule_memory, templates,
                                 W1, b1, W2, b2, Wr, br, log_temp);

    dim3 gC(N_ / TILE_CELLS, B_);
    gss_apply_kernel<<<gC, C_THREADS>>>(cpu_state, out);
}